// round 1
// baseline (speedup 1.0000x reference)
#include <cuda_runtime.h>
#include <cstddef>

#define D 128
#define MAX_NODES 50000

// Static device scratch (no allocations allowed).
__device__ float g_agg[(size_t)MAX_NODES * D];   // 25.6 MB aggregation buffer
__device__ float g_h[(size_t)MAX_NODES * D];     // 25.6 MB layer-0 output
__device__ float g_invdeg[MAX_NODES];
__device__ float g_deg[MAX_NODES];

// ---------------------------------------------------------------------------
// Zero agg (and optionally deg) via grid-stride.
// ---------------------------------------------------------------------------
__global__ void zero_kernel(int n_agg, int also_deg, int n_nodes) {
    int stride = gridDim.x * blockDim.x;
    for (int i = blockIdx.x * blockDim.x + threadIdx.x; i < n_agg; i += stride)
        g_agg[i] = 0.0f;
    if (also_deg) {
        for (int i = blockIdx.x * blockDim.x + threadIdx.x; i < n_nodes; i += stride)
            g_deg[i] = 0.0f;
    }
}

// ---------------------------------------------------------------------------
// In-degree count: one thread per edge.
// ---------------------------------------------------------------------------
__global__ void count_deg_kernel(const int* __restrict__ dst, int E) {
    int e = blockIdx.x * blockDim.x + threadIdx.x;
    if (e < E) atomicAdd(&g_deg[dst[e]], 1.0f);
}

__global__ void finalize_invdeg_kernel(int n) {
    int i = blockIdx.x * blockDim.x + threadIdx.x;
    if (i < n) {
        float d = g_deg[i];
        g_invdeg[i] = (d > 0.0f) ? (1.0f / d) : 0.0f;
    }
}

// ---------------------------------------------------------------------------
// Edge scatter: one warp per edge. Each lane loads 16B of h[src] and does a
// vectorized global reduction into agg[dst]. Both buffers fit in L2.
// ---------------------------------------------------------------------------
__global__ void scatter_kernel(const float* __restrict__ h,
                               const int* __restrict__ src,
                               const int* __restrict__ dst,
                               int E) {
    int gw = (blockIdx.x * blockDim.x + threadIdx.x) >> 5;
    int lane = threadIdx.x & 31;
    if (gw >= E) return;
    int s = __ldg(src + gw);
    int d = __ldg(dst + gw);
    float4 v = __ldg(reinterpret_cast<const float4*>(h + (size_t)s * D) + lane);
    float* p = g_agg + (size_t)d * D + lane * 4;
    asm volatile("red.global.add.v4.f32 [%0], {%1,%2,%3,%4};"
                 :: "l"(p), "f"(v.x), "f"(v.y), "f"(v.z), "f"(v.w)
                 : "memory");
}

// ---------------------------------------------------------------------------
// Fused SAGE GEMM: out = (invdeg .* agg) @ Wl + H @ Wr + mask.*bias, opt ReLU.
// M x 128 output, K = 128 per operand (256 effective). Classic 128x128 tile,
// BK=8, 256 threads, 8x8 register tile per thread, As stored transposed.
// ---------------------------------------------------------------------------
template <bool RELU>
__global__ void __launch_bounds__(256)
sage_gemm_kernel(const float* __restrict__ Ain,   // aggregated features
                 const float* __restrict__ Hin,   // skip-path features
                 const float* __restrict__ Wl,
                 const float* __restrict__ Wr,
                 const float* __restrict__ bias,
                 float* __restrict__ out,
                 int M) {
    constexpr int BM = 128, BN = 128, BK = 8;
    __shared__ float As[BK][BM];
    __shared__ float Bs[BK][BN];

    const int tid = threadIdx.x;
    const int block_row = blockIdx.x * BM;

    // compute-tile mapping: 16x16 threads, each owns 8x8
    const int tr = (tid >> 4) << 3;   // 0..120
    const int tc = (tid & 15) << 3;   // 0..120

    // A-load mapping: 2 threads per row, float4 each (covers 128x8)
    const int arow = tid >> 1;
    const int ac = (tid & 1) * 4;
    // B-load mapping: 8 rows x 32 float4 (covers 8x128)
    const int brow = tid >> 5;
    const int bc = (tid & 31) * 4;

    const int grow_a = block_row + arow;
    const float sA = (grow_a < M) ? g_invdeg[grow_a] : 0.0f;

    float acc[8][8];
#pragma unroll
    for (int i = 0; i < 8; ++i)
#pragma unroll
        for (int j = 0; j < 8; ++j) acc[i][j] = 0.0f;

#pragma unroll 1
    for (int phase = 0; phase < 2; ++phase) {
        const float* A = phase ? Hin : Ain;
        const float* B = phase ? Wr : Wl;
        const float scale = phase ? 1.0f : sA;

#pragma unroll 1
        for (int k0 = 0; k0 < D; k0 += BK) {
            float4 av = make_float4(0.f, 0.f, 0.f, 0.f);
            if (grow_a < M)
                av = *reinterpret_cast<const float4*>(A + (size_t)grow_a * D + k0 + ac);
            float4 bv = *reinterpret_cast<const float4*>(B + (size_t)(k0 + brow) * D + bc);

            __syncthreads();   // protect previous iteration's reads
            As[ac + 0][arow] = av.x * scale;
            As[ac + 1][arow] = av.y * scale;
            As[ac + 2][arow] = av.z * scale;
            As[ac + 3][arow] = av.w * scale;
            *reinterpret_cast<float4*>(&Bs[brow][bc]) = bv;
            __syncthreads();

#pragma unroll
            for (int kk = 0; kk < BK; ++kk) {
                float4 a0 = *reinterpret_cast<const float4*>(&As[kk][tr]);
                float4 a1 = *reinterpret_cast<const float4*>(&As[kk][tr + 4]);
                float4 b0 = *reinterpret_cast<const float4*>(&Bs[kk][tc]);
                float4 b1 = *reinterpret_cast<const float4*>(&Bs[kk][tc + 4]);
                float ra[8] = {a0.x, a0.y, a0.z, a0.w, a1.x, a1.y, a1.z, a1.w};
                float rb[8] = {b0.x, b0.y, b0.z, b0.w, b1.x, b1.y, b1.z, b1.w};
#pragma unroll
                for (int i = 0; i < 8; ++i)
#pragma unroll
                    for (int j = 0; j < 8; ++j)
                        acc[i][j] += ra[i] * rb[j];
            }
        }
    }

    // Epilogue: bias masked by (deg>0), optional ReLU, vectorized stores.
#pragma unroll
    for (int i = 0; i < 8; ++i) {
        int r = block_row + tr + i;
        if (r >= M) break;
        float mask = (g_invdeg[r] > 0.0f) ? 1.0f : 0.0f;
        float v[8];
#pragma unroll
        for (int j = 0; j < 8; ++j) {
            float val = acc[i][j] + mask * bias[tc + j];
            if (RELU) val = fmaxf(val, 0.0f);
            v[j] = val;
        }
        float* po = out + (size_t)r * D + tc;
        *reinterpret_cast<float4*>(po) = make_float4(v[0], v[1], v[2], v[3]);
        *reinterpret_cast<float4*>(po + 4) = make_float4(v[4], v[5], v[6], v[7]);
    }
}

// ---------------------------------------------------------------------------
// Launch sequence (graph-capturable; all on default stream).
// ---------------------------------------------------------------------------
extern "C" void kernel_launch(void* const* d_in, const int* in_sizes, int n_in,
                              void* d_out, int out_size) {
    const float* x   = (const float*)d_in[0];
    const int*   ei  = (const int*)d_in[1];
    const float* W0l = (const float*)d_in[2];
    const float* b0l = (const float*)d_in[3];
    const float* W0r = (const float*)d_in[4];
    const float* W1l = (const float*)d_in[5];
    const float* b1l = (const float*)d_in[6];
    const float* W1r = (const float*)d_in[7];
    float* out = (float*)d_out;

    const int E = in_sizes[1] / 2;
    const int M = in_sizes[0] / D;
    const int* src = ei;
    const int* dst = ei + E;

    float* agg_ptr = nullptr;
    float* h_ptr = nullptr;
    cudaGetSymbolAddress((void**)&agg_ptr, g_agg);
    cudaGetSymbolAddress((void**)&h_ptr, g_h);

    const int n_agg = M * D;
    const int zero_blocks = 4096;
    const int deg_blocks = (E + 255) / 256;
    const int inv_blocks = (M + 255) / 256;
    const int scat_blocks = (E * 32 + 255) / 256;   // one warp per edge
    const int gemm_blocks = (M + 127) / 128;

    // Degree (once) + zero agg
    zero_kernel<<<zero_blocks, 256>>>(n_agg, 1, M);
    count_deg_kernel<<<deg_blocks, 256>>>(dst, E);
    finalize_invdeg_kernel<<<inv_blocks, 256>>>(M);

    // Layer 0
    scatter_kernel<<<scat_blocks, 256>>>(x, src, dst, E);
    sage_gemm_kernel<true><<<gemm_blocks, 256>>>(agg_ptr, x, W0l, W0r, b0l, h_ptr, M);

    // Layer 1
    zero_kernel<<<zero_blocks, 256>>>(n_agg, 0, M);
    scatter_kernel<<<scat_blocks, 256>>>(h_ptr, src, dst, E);
    sage_gemm_kernel<false><<<gemm_blocks, 256>>>(agg_ptr, h_ptr, W1l, W1r, b1l, out, M);
}

// round 2
// speedup vs baseline: 1.3202x; 1.3202x over previous
#include <cuda_runtime.h>
#include <cstddef>

#define D 128
#define MAX_NODES 50000
#define MAX_EDGES 800000

// Static device scratch (no allocations allowed).
__device__ float g_agg[(size_t)MAX_NODES * D];   // pre-averaged aggregation
__device__ float g_h[(size_t)MAX_NODES * D];     // layer-0 output
__device__ int   g_degi[MAX_NODES];
__device__ int   g_off[MAX_NODES];
__device__ int   g_cur[MAX_NODES];
__device__ int   g_ssrc[MAX_EDGES];

// ---------------------------------------------------------------------------
// Setup kernels: degree histogram -> prefix scan -> CSR fill.
// ---------------------------------------------------------------------------
__global__ void zero_int_kernel(int n) {
    int i = blockIdx.x * blockDim.x + threadIdx.x;
    if (i < n) { g_degi[i] = 0; g_cur[i] = 0; }
}

__global__ void count_deg_kernel(const int* __restrict__ dst, int E) {
    int e = blockIdx.x * blockDim.x + threadIdx.x;
    if (e < E) atomicAdd(&g_degi[dst[e]], 1);
}

#define SCAN_THREADS 1024
__global__ void scan_kernel(int n) {
    __shared__ int sums[SCAN_THREADS];
    int t = threadIdx.x;
    int per = (n + SCAN_THREADS - 1) / SCAN_THREADS;
    int beg = t * per;
    int end = beg + per; if (end > n) end = n;
    int s = 0;
    for (int i = beg; i < end; ++i) s += g_degi[i];
    sums[t] = s;
    __syncthreads();
    // Hillis-Steele inclusive scan
    for (int ofs = 1; ofs < SCAN_THREADS; ofs <<= 1) {
        int v = (t >= ofs) ? sums[t - ofs] : 0;
        __syncthreads();
        sums[t] += v;
        __syncthreads();
    }
    int run = (t == 0) ? 0 : sums[t - 1];
    for (int i = beg; i < end; ++i) {
        g_off[i] = run;
        run += g_degi[i];
    }
}

__global__ void fill_csr_kernel(const int* __restrict__ src,
                                const int* __restrict__ dst, int E) {
    int e = blockIdx.x * blockDim.x + threadIdx.x;
    if (e < E) {
        int d = dst[e];
        int p = atomicAdd(&g_cur[d], 1);
        g_ssrc[g_off[d] + p] = src[e];
    }
}

// ---------------------------------------------------------------------------
// Gather-aggregate: one warp per destination node; register accumulation;
// single write of the averaged row. No atomics, no agg zeroing needed.
// ---------------------------------------------------------------------------
__global__ void gather_kernel(const float* __restrict__ h,
                              float* __restrict__ agg, int M) {
    int w = (blockIdx.x * blockDim.x + threadIdx.x) >> 5;
    int lane = threadIdx.x & 31;
    if (w >= M) return;
    int beg = g_off[w];
    int dg = g_degi[w];

    float4 a0 = make_float4(0.f, 0.f, 0.f, 0.f);
    float4 a1 = a0, a2 = a0, a3 = a0;
    int i = 0;
    for (; i + 4 <= dg; i += 4) {
        int s0 = g_ssrc[beg + i];
        int s1 = g_ssrc[beg + i + 1];
        int s2 = g_ssrc[beg + i + 2];
        int s3 = g_ssrc[beg + i + 3];
        float4 v0 = __ldg(reinterpret_cast<const float4*>(h + (size_t)s0 * D) + lane);
        float4 v1 = __ldg(reinterpret_cast<const float4*>(h + (size_t)s1 * D) + lane);
        float4 v2 = __ldg(reinterpret_cast<const float4*>(h + (size_t)s2 * D) + lane);
        float4 v3 = __ldg(reinterpret_cast<const float4*>(h + (size_t)s3 * D) + lane);
        a0.x += v0.x; a0.y += v0.y; a0.z += v0.z; a0.w += v0.w;
        a1.x += v1.x; a1.y += v1.y; a1.z += v1.z; a1.w += v1.w;
        a2.x += v2.x; a2.y += v2.y; a2.z += v2.z; a2.w += v2.w;
        a3.x += v3.x; a3.y += v3.y; a3.z += v3.z; a3.w += v3.w;
    }
    for (; i < dg; ++i) {
        int s = g_ssrc[beg + i];
        float4 v = __ldg(reinterpret_cast<const float4*>(h + (size_t)s * D) + lane);
        a0.x += v.x; a0.y += v.y; a0.z += v.z; a0.w += v.w;
    }
    float inv = (dg > 0) ? 1.0f / (float)dg : 0.0f;
    float4 r;
    r.x = (a0.x + a1.x + a2.x + a3.x) * inv;
    r.y = (a0.y + a1.y + a2.y + a3.y) * inv;
    r.z = (a0.z + a1.z + a2.z + a3.z) * inv;
    r.w = (a0.w + a1.w + a2.w + a3.w) * inv;
    *(reinterpret_cast<float4*>(agg + (size_t)w * D) + lane) = r;
}

// ---------------------------------------------------------------------------
// Fused SAGE GEMM via 3xTF32 mma.sync: out = Agg@Wl + H@Wr + mask.*bias.
// 128x128 block tile, K = 2x128 (two phases), BK=16, 8 warps (2x4),
// warp tile 64x32, m16n8k8 tf32 fragments, fp32 accumulation.
// ---------------------------------------------------------------------------
__device__ __forceinline__ unsigned f2tf(float f) {
    unsigned u;
    asm("cvt.rna.tf32.f32 %0, %1;" : "=r"(u) : "f"(f));
    return u;
}

#define MMA_TF32(c, a, b)                                                      \
    asm volatile(                                                              \
        "mma.sync.aligned.m16n8k8.row.col.f32.tf32.tf32.f32 "                  \
        "{%0,%1,%2,%3},{%4,%5,%6,%7},{%8,%9},{%0,%1,%2,%3};"                   \
        : "+f"((c)[0]), "+f"((c)[1]), "+f"((c)[2]), "+f"((c)[3])               \
        : "r"((a)[0]), "r"((a)[1]), "r"((a)[2]), "r"((a)[3]),                  \
          "r"((b)[0]), "r"((b)[1]))

#define AS_STRIDE 20   // 16 + 4 pad: conflict-free frag reads
#define BS_STRIDE 136  // 128 + 8 pad: conflict-free frag reads

template <bool RELU>
__global__ void __launch_bounds__(256, 2)
sage_mma_kernel(const float* __restrict__ Agg, const float* __restrict__ Hin,
                const float* __restrict__ Wl, const float* __restrict__ Wr,
                const float* __restrict__ bias, float* __restrict__ out,
                int M) {
    __shared__ float As_hi[128 * AS_STRIDE];
    __shared__ float As_lo[128 * AS_STRIDE];
    __shared__ float Bs_hi[16 * BS_STRIDE];
    __shared__ float Bs_lo[16 * BS_STRIDE];

    const int tid = threadIdx.x;
    const int warp = tid >> 5;
    const int lane = tid & 31;
    const int gid = lane >> 2;   // 0..7
    const int tig = lane & 3;    // 0..3
    const int wm = (warp >> 2) * 64;   // warp m offset
    const int wn = (warp & 3) * 32;    // warp n offset
    const int block_row = blockIdx.x * 128;

    // A load mapping: 2 threads/row, 8 floats each
    const int alr = tid >> 1;
    const int alc = (tid & 1) * 8;
    // B load mapping: 16 threads/row, 8 floats each
    const int blr = tid >> 4;
    const int blc = (tid & 15) * 8;
    const int grow = block_row + alr;

    float acc[4][4][4];
#pragma unroll
    for (int i = 0; i < 4; ++i)
#pragma unroll
        for (int j = 0; j < 4; ++j)
#pragma unroll
            for (int r = 0; r < 4; ++r) acc[i][j][r] = 0.0f;

#pragma unroll 1
    for (int phase = 0; phase < 2; ++phase) {
        const float* A = phase ? Hin : Agg;
        const float* B = phase ? Wr : Wl;

#pragma unroll 1
        for (int k0 = 0; k0 < D; k0 += 16) {
            float va[8];
            if (grow < M) {
                float4 t0 = *reinterpret_cast<const float4*>(A + (size_t)grow * D + k0 + alc);
                float4 t1 = *reinterpret_cast<const float4*>(A + (size_t)grow * D + k0 + alc + 4);
                va[0] = t0.x; va[1] = t0.y; va[2] = t0.z; va[3] = t0.w;
                va[4] = t1.x; va[5] = t1.y; va[6] = t1.z; va[7] = t1.w;
            } else {
#pragma unroll
                for (int j = 0; j < 8; ++j) va[j] = 0.0f;
            }
            float4 w0 = *reinterpret_cast<const float4*>(B + (size_t)(k0 + blr) * D + blc);
            float4 w1 = *reinterpret_cast<const float4*>(B + (size_t)(k0 + blr) * D + blc + 4);
            float wb[8] = {w0.x, w0.y, w0.z, w0.w, w1.x, w1.y, w1.z, w1.w};

            __syncthreads();   // previous iteration's smem reads done
#pragma unroll
            for (int j = 0; j < 8; ++j) {
                float hi = __uint_as_float(f2tf(va[j]));
                As_hi[alr * AS_STRIDE + alc + j] = hi;
                As_lo[alr * AS_STRIDE + alc + j] = __uint_as_float(f2tf(va[j] - hi));
            }
#pragma unroll
            for (int j = 0; j < 8; ++j) {
                float hi = __uint_as_float(f2tf(wb[j]));
                Bs_hi[blr * BS_STRIDE + blc + j] = hi;
                Bs_lo[blr * BS_STRIDE + blc + j] = __uint_as_float(f2tf(wb[j] - hi));
            }
            __syncthreads();

#pragma unroll
            for (int ks = 0; ks < 16; ks += 8) {
                unsigned bh[4][2], bl[4][2];
#pragma unroll
                for (int nt = 0; nt < 4; ++nt) {
                    int nc = wn + nt * 8 + gid;
                    bh[nt][0] = __float_as_uint(Bs_hi[(ks + tig) * BS_STRIDE + nc]);
                    bh[nt][1] = __float_as_uint(Bs_hi[(ks + tig + 4) * BS_STRIDE + nc]);
                    bl[nt][0] = __float_as_uint(Bs_lo[(ks + tig) * BS_STRIDE + nc]);
                    bl[nt][1] = __float_as_uint(Bs_lo[(ks + tig + 4) * BS_STRIDE + nc]);
                }
#pragma unroll
                for (int mt = 0; mt < 4; ++mt) {
                    int r0 = (wm + mt * 16 + gid) * AS_STRIDE;
                    int r8 = r0 + 8 * AS_STRIDE;
                    unsigned ah[4], al[4];
                    ah[0] = __float_as_uint(As_hi[r0 + ks + tig]);
                    ah[1] = __float_as_uint(As_hi[r8 + ks + tig]);
                    ah[2] = __float_as_uint(As_hi[r0 + ks + tig + 4]);
                    ah[3] = __float_as_uint(As_hi[r8 + ks + tig + 4]);
                    al[0] = __float_as_uint(As_lo[r0 + ks + tig]);
                    al[1] = __float_as_uint(As_lo[r8 + ks + tig]);
                    al[2] = __float_as_uint(As_lo[r0 + ks + tig + 4]);
                    al[3] = __float_as_uint(As_lo[r8 + ks + tig + 4]);
#pragma unroll
                    for (int nt = 0; nt < 4; ++nt) {
                        MMA_TF32(acc[mt][nt], ah, bh[nt]);
                        MMA_TF32(acc[mt][nt], ah, bl[nt]);
                        MMA_TF32(acc[mt][nt], al, bh[nt]);
                    }
                }
            }
        }
    }

    // Epilogue: + mask(deg>0)*bias, optional ReLU, float2 stores.
#pragma unroll
    for (int mt = 0; mt < 4; ++mt) {
#pragma unroll
        for (int nt = 0; nt < 4; ++nt) {
            int row0 = block_row + wm + mt * 16 + gid;
            int row1 = row0 + 8;
            int col = wn + nt * 8 + tig * 2;
            float b0v = bias[col];
            float b1v = bias[col + 1];
            if (row0 < M) {
                float m0 = (g_degi[row0] > 0) ? 1.0f : 0.0f;
                float x0 = acc[mt][nt][0] + m0 * b0v;
                float x1 = acc[mt][nt][1] + m0 * b1v;
                if (RELU) { x0 = fmaxf(x0, 0.0f); x1 = fmaxf(x1, 0.0f); }
                *reinterpret_cast<float2*>(out + (size_t)row0 * D + col) = make_float2(x0, x1);
            }
            if (row1 < M) {
                float m1 = (g_degi[row1] > 0) ? 1.0f : 0.0f;
                float x2 = acc[mt][nt][2] + m1 * b0v;
                float x3 = acc[mt][nt][3] + m1 * b1v;
                if (RELU) { x2 = fmaxf(x2, 0.0f); x3 = fmaxf(x3, 0.0f); }
                *reinterpret_cast<float2*>(out + (size_t)row1 * D + col) = make_float2(x2, x3);
            }
        }
    }
}

// ---------------------------------------------------------------------------
// Launch sequence (graph-capturable; all on default stream).
// ---------------------------------------------------------------------------
extern "C" void kernel_launch(void* const* d_in, const int* in_sizes, int n_in,
                              void* d_out, int out_size) {
    const float* x   = (const float*)d_in[0];
    const int*   ei  = (const int*)d_in[1];
    const float* W0l = (const float*)d_in[2];
    const float* b0l = (const float*)d_in[3];
    const float* W0r = (const float*)d_in[4];
    const float* W1l = (const float*)d_in[5];
    const float* b1l = (const float*)d_in[6];
    const float* W1r = (const float*)d_in[7];
    float* out = (float*)d_out;

    const int E = in_sizes[1] / 2;
    const int M = in_sizes[0] / D;
    const int* src = ei;
    const int* dst = ei + E;

    float* agg_ptr = nullptr;
    float* h_ptr = nullptr;
    cudaGetSymbolAddress((void**)&agg_ptr, g_agg);
    cudaGetSymbolAddress((void**)&h_ptr, g_h);

    const int nb = (M + 255) / 256;
    const int eb = (E + 255) / 256;
    const int gatherb = (M * 32 + 255) / 256;   // one warp per node
    const int gemmb = (M + 127) / 128;

    // CSR build (once per launch)
    zero_int_kernel<<<nb, 256>>>(M);
    count_deg_kernel<<<eb, 256>>>(dst, E);
    scan_kernel<<<1, SCAN_THREADS>>>(M);
    fill_csr_kernel<<<eb, 256>>>(src, dst, E);

    // Layer 0
    gather_kernel<<<gatherb, 256>>>(x, agg_ptr, M);
    sage_mma_kernel<true><<<gemmb, 256>>>(agg_ptr, x, W0l, W0r, b0l, h_ptr, M);

    // Layer 1
    gather_kernel<<<gatherb, 256>>>(h_ptr, agg_ptr, M);
    sage_mma_kernel<false><<<gemmb, 256>>>(agg_ptr, h_ptr, W1l, W1r, b1l, out, M);
}

// round 3
// speedup vs baseline: 1.5083x; 1.1425x over previous
#include <cuda_runtime.h>
#include <cuda_bf16.h>
#include <cstddef>

#define D 128
#define MAX_NODES 50000
#define MAX_EDGES 800000

typedef unsigned int u32;

// Static device scratch (no allocations allowed).
__device__ float g_agg[(size_t)MAX_NODES * D];   // pre-averaged aggregation
__device__ float g_h[(size_t)MAX_NODES * D];     // layer-0 output
__device__ int   g_degi[MAX_NODES];
__device__ int   g_off[MAX_NODES];
__device__ int   g_cur[MAX_NODES];
__device__ int   g_ssrc[MAX_EDGES];

// ---------------------------------------------------------------------------
// Setup: degree histogram -> prefix scan (also seeds g_cur) -> CSR fill.
// ---------------------------------------------------------------------------
__global__ void zero_int_kernel(int n) {
    int i = blockIdx.x * blockDim.x + threadIdx.x;
    if (i < n) g_degi[i] = 0;
}

__global__ void count_deg_kernel(const int* __restrict__ dst, int E) {
    int e = blockIdx.x * blockDim.x + threadIdx.x;
    if (e < E) atomicAdd(&g_degi[dst[e]], 1);
}

#define SCAN_THREADS 1024
__global__ void scan_kernel(int n) {
    __shared__ int sums[SCAN_THREADS];
    int t = threadIdx.x;
    int per = (n + SCAN_THREADS - 1) / SCAN_THREADS;
    int beg = t * per;
    int end = beg + per; if (end > n) end = n;
    int s = 0;
    for (int i = beg; i < end; ++i) s += g_degi[i];
    sums[t] = s;
    __syncthreads();
    for (int ofs = 1; ofs < SCAN_THREADS; ofs <<= 1) {
        int v = (t >= ofs) ? sums[t - ofs] : 0;
        __syncthreads();
        sums[t] += v;
        __syncthreads();
    }
    int run = (t == 0) ? 0 : sums[t - 1];
    for (int i = beg; i < end; ++i) {
        g_off[i] = run;
        g_cur[i] = run;      // fill_csr's atomicAdd returns the slot directly
        run += g_degi[i];
    }
}

__global__ void fill_csr_kernel(const int* __restrict__ src,
                                const int* __restrict__ dst, int E) {
    int e = blockIdx.x * blockDim.x + threadIdx.x;
    if (e < E) {
        int p = atomicAdd(&g_cur[dst[e]], 1);
        g_ssrc[p] = src[e];
    }
}

// ---------------------------------------------------------------------------
// Gather-aggregate: one warp per destination node; register accumulation;
// single write of the averaged row. No atomics.
// ---------------------------------------------------------------------------
__global__ void gather_kernel(const float* __restrict__ h,
                              float* __restrict__ agg, int M) {
    int w = (blockIdx.x * blockDim.x + threadIdx.x) >> 5;
    int lane = threadIdx.x & 31;
    if (w >= M) return;
    int beg = g_off[w];
    int dg = g_degi[w];

    float4 a0 = make_float4(0.f, 0.f, 0.f, 0.f);
    float4 a1 = a0, a2 = a0, a3 = a0;
    int i = 0;
    for (; i + 4 <= dg; i += 4) {
        int s0 = g_ssrc[beg + i];
        int s1 = g_ssrc[beg + i + 1];
        int s2 = g_ssrc[beg + i + 2];
        int s3 = g_ssrc[beg + i + 3];
        float4 v0 = __ldg(reinterpret_cast<const float4*>(h + (size_t)s0 * D) + lane);
        float4 v1 = __ldg(reinterpret_cast<const float4*>(h + (size_t)s1 * D) + lane);
        float4 v2 = __ldg(reinterpret_cast<const float4*>(h + (size_t)s2 * D) + lane);
        float4 v3 = __ldg(reinterpret_cast<const float4*>(h + (size_t)s3 * D) + lane);
        a0.x += v0.x; a0.y += v0.y; a0.z += v0.z; a0.w += v0.w;
        a1.x += v1.x; a1.y += v1.y; a1.z += v1.z; a1.w += v1.w;
        a2.x += v2.x; a2.y += v2.y; a2.z += v2.z; a2.w += v2.w;
        a3.x += v3.x; a3.y += v3.y; a3.z += v3.z; a3.w += v3.w;
    }
    for (; i < dg; ++i) {
        int s = g_ssrc[beg + i];
        float4 v = __ldg(reinterpret_cast<const float4*>(h + (size_t)s * D) + lane);
        a0.x += v.x; a0.y += v.y; a0.z += v.z; a0.w += v.w;
    }
    float inv = (dg > 0) ? 1.0f / (float)dg : 0.0f;
    float4 r;
    r.x = (a0.x + a1.x + a2.x + a3.x) * inv;
    r.y = (a0.y + a1.y + a2.y + a3.y) * inv;
    r.z = (a0.z + a1.z + a2.z + a3.z) * inv;
    r.w = (a0.w + a1.w + a2.w + a3.w) * inv;
    *(reinterpret_cast<float4*>(agg + (size_t)w * D) + lane) = r;
}

// ---------------------------------------------------------------------------
// Fused SAGE GEMM via 3xBF16 mma.sync.m16n8k16:
//   out = Agg@Wl + H@Wr + mask.*bias (+ReLU).
// Split a = ah + al (both bf16): a*b ~= ah*bh + ah*bl + al*bh (err ~2^-18).
// 128x128 block tile, 2 K-phases of 128, BK=32, 8 warps, warp tile 64x32.
// Smem stores packed bf16x2 along K.
// ---------------------------------------------------------------------------
__device__ __forceinline__ void split_pack(float x, float y, u32& hi, u32& lo) {
    __nv_bfloat162 h2 = __floats2bfloat162_rn(x, y);
    float hx = __bfloat162float(__low2bfloat16(h2));
    float hy = __bfloat162float(__high2bfloat16(h2));
    __nv_bfloat162 l2 = __floats2bfloat162_rn(x - hx, y - hy);
    hi = *reinterpret_cast<u32*>(&h2);
    lo = *reinterpret_cast<u32*>(&l2);
}

#define MMA_BF16(c, a, b)                                                      \
    asm volatile(                                                              \
        "mma.sync.aligned.m16n8k16.row.col.f32.bf16.bf16.f32 "                 \
        "{%0,%1,%2,%3},{%4,%5,%6,%7},{%8,%9},{%0,%1,%2,%3};"                   \
        : "+f"((c)[0]), "+f"((c)[1]), "+f"((c)[2]), "+f"((c)[3])               \
        : "r"((a)[0]), "r"((a)[1]), "r"((a)[2]), "r"((a)[3]),                  \
          "r"((b)[0]), "r"((b)[1]))

#define AS_STRIDE 20   // 16 packed words + 4 pad: conflict-free frag reads
#define BS_STRIDE 136  // 128 packed cols + 8 pad: conflict-free frag reads

template <bool RELU>
__global__ void __launch_bounds__(256, 2)
sage_mma_kernel(const float* __restrict__ Agg, const float* __restrict__ Hin,
                const float* __restrict__ Wl, const float* __restrict__ Wr,
                const float* __restrict__ bias, float* __restrict__ out,
                int M) {
    __shared__ u32 As_hi[128 * AS_STRIDE];
    __shared__ u32 As_lo[128 * AS_STRIDE];
    __shared__ u32 Bs_hi[16 * BS_STRIDE];
    __shared__ u32 Bs_lo[16 * BS_STRIDE];

    const int tid = threadIdx.x;
    const int warp = tid >> 5;
    const int lane = tid & 31;
    const int gid = lane >> 2;         // 0..7
    const int tig = lane & 3;          // 0..3
    const int wm = (warp >> 2) * 64;   // warp m offset
    const int wn = (warp & 3) * 32;    // warp n offset
    const int block_row = blockIdx.x * 128;

    // A load: 2 threads/row; each covers 16 K-elems (8 packed words)
    const int alr = tid >> 1;
    const int ahalf = (tid & 1) * 16;      // K offset in elems
    const int apk = (tid & 1) * 8;         // packed word offset
    // B load: thread t -> packed K-row p = t>>4 (covers k rows 2p,2p+1),
    //         cols (t&15)*8 .. +8
    const int bp = tid >> 4;
    const int bc = (tid & 15) * 8;
    const int grow = block_row + alr;

    float acc[4][4][4];
#pragma unroll
    for (int i = 0; i < 4; ++i)
#pragma unroll
        for (int j = 0; j < 4; ++j)
#pragma unroll
            for (int r = 0; r < 4; ++r) acc[i][j][r] = 0.0f;

#pragma unroll 1
    for (int phase = 0; phase < 2; ++phase) {
        const float* A = phase ? Hin : Agg;
        const float* B = phase ? Wr : Wl;

#pragma unroll 1
        for (int k0 = 0; k0 < D; k0 += 32) {
            // global loads (16 floats A, 16 floats B per thread)
            float va[16];
            if (grow < M) {
                const float* ap = A + (size_t)grow * D + k0 + ahalf;
#pragma unroll
                for (int q = 0; q < 4; ++q) {
                    float4 t = *reinterpret_cast<const float4*>(ap + q * 4);
                    va[q * 4 + 0] = t.x; va[q * 4 + 1] = t.y;
                    va[q * 4 + 2] = t.z; va[q * 4 + 3] = t.w;
                }
            } else {
#pragma unroll
                for (int q = 0; q < 16; ++q) va[q] = 0.0f;
            }
            float r0[8], r1[8];
            {
                const float* bp0 = B + (size_t)(k0 + 2 * bp) * D + bc;
                const float* bp1 = bp0 + D;
                float4 t0 = *reinterpret_cast<const float4*>(bp0);
                float4 t1 = *reinterpret_cast<const float4*>(bp0 + 4);
                float4 t2 = *reinterpret_cast<const float4*>(bp1);
                float4 t3 = *reinterpret_cast<const float4*>(bp1 + 4);
                r0[0]=t0.x; r0[1]=t0.y; r0[2]=t0.z; r0[3]=t0.w;
                r0[4]=t1.x; r0[5]=t1.y; r0[6]=t1.z; r0[7]=t1.w;
                r1[0]=t2.x; r1[1]=t2.y; r1[2]=t2.z; r1[3]=t2.w;
                r1[4]=t3.x; r1[5]=t3.y; r1[6]=t3.z; r1[7]=t3.w;
            }

            __syncthreads();   // previous iteration's smem reads done
#pragma unroll
            for (int p = 0; p < 8; ++p) {
                u32 hi, lo;
                split_pack(va[2 * p], va[2 * p + 1], hi, lo);
                As_hi[alr * AS_STRIDE + apk + p] = hi;
                As_lo[alr * AS_STRIDE + apk + p] = lo;
            }
#pragma unroll
            for (int j = 0; j < 8; ++j) {
                u32 hi, lo;
                split_pack(r0[j], r1[j], hi, lo);   // low half = even k
                Bs_hi[bp * BS_STRIDE + bc + j] = hi;
                Bs_lo[bp * BS_STRIDE + bc + j] = lo;
            }
            __syncthreads();

#pragma unroll
            for (int ks2 = 0; ks2 < 16; ks2 += 8) {   // two K=16 steps
                u32 bh[4][2], bl[4][2];
#pragma unroll
                for (int nt = 0; nt < 4; ++nt) {
                    int nc = wn + nt * 8 + gid;
                    bh[nt][0] = Bs_hi[(ks2 + tig) * BS_STRIDE + nc];
                    bh[nt][1] = Bs_hi[(ks2 + tig + 4) * BS_STRIDE + nc];
                    bl[nt][0] = Bs_lo[(ks2 + tig) * BS_STRIDE + nc];
                    bl[nt][1] = Bs_lo[(ks2 + tig + 4) * BS_STRIDE + nc];
                }
#pragma unroll
                for (int mt = 0; mt < 4; ++mt) {
                    int rr0 = (wm + mt * 16 + gid) * AS_STRIDE;
                    int rr8 = rr0 + 8 * AS_STRIDE;
                    u32 ah[4], al[4];
                    ah[0] = As_hi[rr0 + ks2 + tig];
                    ah[1] = As_hi[rr8 + ks2 + tig];
                    ah[2] = As_hi[rr0 + ks2 + tig + 4];
                    ah[3] = As_hi[rr8 + ks2 + tig + 4];
                    al[0] = As_lo[rr0 + ks2 + tig];
                    al[1] = As_lo[rr8 + ks2 + tig];
                    al[2] = As_lo[rr0 + ks2 + tig + 4];
                    al[3] = As_lo[rr8 + ks2 + tig + 4];
#pragma unroll
                    for (int nt = 0; nt < 4; ++nt) {
                        MMA_BF16(acc[mt][nt], ah, bh[nt]);
                        MMA_BF16(acc[mt][nt], ah, bl[nt]);
                        MMA_BF16(acc[mt][nt], al, bh[nt]);
                    }
                }
            }
        }
    }

    // Epilogue: + mask(deg>0)*bias, optional ReLU, float2 stores.
#pragma unroll
    for (int mt = 0; mt < 4; ++mt) {
#pragma unroll
        for (int nt = 0; nt < 4; ++nt) {
            int row0 = block_row + wm + mt * 16 + gid;
            int row1 = row0 + 8;
            int col = wn + nt * 8 + tig * 2;
            float b0v = bias[col];
            float b1v = bias[col + 1];
            if (row0 < M) {
                float m0 = (g_degi[row0] > 0) ? 1.0f : 0.0f;
                float x0 = acc[mt][nt][0] + m0 * b0v;
                float x1 = acc[mt][nt][1] + m0 * b1v;
                if (RELU) { x0 = fmaxf(x0, 0.0f); x1 = fmaxf(x1, 0.0f); }
                *reinterpret_cast<float2*>(out + (size_t)row0 * D + col) = make_float2(x0, x1);
            }
            if (row1 < M) {
                float m1 = (g_degi[row1] > 0) ? 1.0f : 0.0f;
                float x2 = acc[mt][nt][2] + m1 * b0v;
                float x3 = acc[mt][nt][3] + m1 * b1v;
                if (RELU) { x2 = fmaxf(x2, 0.0f); x3 = fmaxf(x3, 0.0f); }
                *reinterpret_cast<float2*>(out + (size_t)row1 * D + col) = make_float2(x2, x3);
            }
        }
    }
}

// ---------------------------------------------------------------------------
// Launch sequence (graph-capturable; all on default stream).
// ---------------------------------------------------------------------------
extern "C" void kernel_launch(void* const* d_in, const int* in_sizes, int n_in,
                              void* d_out, int out_size) {
    const float* x   = (const float*)d_in[0];
    const int*   ei  = (const int*)d_in[1];
    const float* W0l = (const float*)d_in[2];
    const float* b0l = (const float*)d_in[3];
    const float* W0r = (const float*)d_in[4];
    const float* W1l = (const float*)d_in[5];
    const float* b1l = (const float*)d_in[6];
    const float* W1r = (const float*)d_in[7];
    float* out = (float*)d_out;

    const int E = in_sizes[1] / 2;
    const int M = in_sizes[0] / D;
    const int* src = ei;
    const int* dst = ei + E;

    float* agg_ptr = nullptr;
    float* h_ptr = nullptr;
    cudaGetSymbolAddress((void**)&agg_ptr, g_agg);
    cudaGetSymbolAddress((void**)&h_ptr, g_h);

    const int nb = (M + 255) / 256;
    const int eb = (E + 255) / 256;
    const int gatherb = (M * 32 + 255) / 256;   // one warp per node
    const int gemmb = (M + 127) / 128;

    // CSR build (once per launch)
    zero_int_kernel<<<nb, 256>>>(M);
    count_deg_kernel<<<eb, 256>>>(dst, E);
    scan_kernel<<<1, SCAN_THREADS>>>(M);
    fill_csr_kernel<<<eb, 256>>>(src, dst, E);

    // Layer 0
    gather_kernel<<<gatherb, 256>>>(x, agg_ptr, M);
    sage_mma_kernel<true><<<gemmb, 256>>>(agg_ptr, x, W0l, W0r, b0l, h_ptr, M);

    // Layer 1
    gather_kernel<<<gatherb, 256>>>(h_ptr, agg_ptr, M);
    sage_mma_kernel<false><<<gemmb, 256>>>(agg_ptr, h_ptr, W1l, W1r, b1l, out, M);
}

// round 5
// speedup vs baseline: 2.0732x; 1.3745x over previous
#include <cuda_runtime.h>
#include <cuda_bf16.h>
#include <cstddef>
#include <cstdint>

#define D 128
#define MAX_NODES 50000
#define MAX_EDGES 800000

typedef unsigned int u32;

// Static device scratch (no allocations allowed).
__device__ float g_agg[(size_t)MAX_NODES * D];
__device__ float g_h[(size_t)MAX_NODES * D];
__device__ int   g_degi[MAX_NODES];
__device__ int   g_off[MAX_NODES];
__device__ int   g_cur[MAX_NODES];
__device__ int   g_ssrc[MAX_EDGES];
__device__ int   g_part[64];
// Pre-split packed weights: [layer][plane hi/lo][kp][n], u32 = bf16x2(k=2kp, k=2kp+1).
// K = 256 = Wl (k<128) | Wr (k>=128), transposed to n-major rows of packed-k words.
__device__ u32 g_Bp[2][2][128][128];

// ---------------------------------------------------------------------------
// Setup: degree histogram -> multi-block scan (seeds g_cur) -> CSR fill.
// ---------------------------------------------------------------------------
__global__ void zero_int_kernel(int n) {
    int i = blockIdx.x * blockDim.x + threadIdx.x;
    if (i < n) g_degi[i] = 0;
}

__global__ void count_deg_kernel(const int* __restrict__ dst, int E) {
    int e = blockIdx.x * blockDim.x + threadIdx.x;
    if (e < E) atomicAdd(&g_degi[dst[e]], 1);
}

#define SCAN_BLK 1024
__global__ void scan_part_kernel(int n) {
    __shared__ int red[SCAN_BLK];
    int tid = threadIdx.x;
    int i = blockIdx.x * SCAN_BLK + tid;
    red[tid] = (i < n) ? g_degi[i] : 0;
    __syncthreads();
#pragma unroll
    for (int ofs = SCAN_BLK / 2; ofs > 0; ofs >>= 1) {
        if (tid < ofs) red[tid] += red[tid + ofs];
        __syncthreads();
    }
    if (tid == 0) g_part[blockIdx.x] = red[0];
}

__global__ void scan_base_kernel(int nb) {
    if (threadIdx.x == 0) {
        int run = 0;
        for (int i = 0; i < nb; ++i) { int t = g_part[i]; g_part[i] = run; run += t; }
    }
}

__global__ void scan_write_kernel(int n) {
    __shared__ int s[SCAN_BLK];
    int tid = threadIdx.x;
    int i = blockIdx.x * SCAN_BLK + tid;
    int v = (i < n) ? g_degi[i] : 0;
    s[tid] = v;
    __syncthreads();
    for (int ofs = 1; ofs < SCAN_BLK; ofs <<= 1) {
        int t = (tid >= ofs) ? s[tid - ofs] : 0;
        __syncthreads();
        s[tid] += t;
        __syncthreads();
    }
    int excl = s[tid] - v + g_part[blockIdx.x];
    if (i < n) { g_off[i] = excl; g_cur[i] = excl; }
}

__global__ void fill_csr_kernel(const int* __restrict__ src,
                                const int* __restrict__ dst, int E) {
    int e = blockIdx.x * blockDim.x + threadIdx.x;
    if (e < E) {
        int p = atomicAdd(&g_cur[dst[e]], 1);
        g_ssrc[p] = src[e];
    }
}

// ---------------------------------------------------------------------------
// Weight conversion: pack W[k][n] -> g_Bp[layer][plane][kp][n] (bf16x2 over k).
// grid = 256 (layer*128 + kp), block = 128 (n).
// ---------------------------------------------------------------------------
__global__ void convert_w_kernel(const float* __restrict__ W0l,
                                 const float* __restrict__ W0r,
                                 const float* __restrict__ W1l,
                                 const float* __restrict__ W1r) {
    int kp = blockIdx.x & 127;
    int layer = blockIdx.x >> 7;
    int n = threadIdx.x;
    int k0 = 2 * kp;                 // 0..254, both k in same half
    const float* W = layer ? (k0 < D ? W1l : W1r) : (k0 < D ? W0l : W0r);
    float v0 = W[(size_t)(k0 & (D - 1)) * D + n];
    float v1 = W[(size_t)((k0 + 1) & (D - 1)) * D + n];
    __nv_bfloat162 h2 = __floats2bfloat162_rn(v0, v1);
    float hx = __bfloat162float(__low2bfloat16(h2));
    float hy = __bfloat162float(__high2bfloat16(h2));
    __nv_bfloat162 l2 = __floats2bfloat162_rn(v0 - hx, v1 - hy);
    g_Bp[layer][0][kp][n] = *reinterpret_cast<u32*>(&h2);
    g_Bp[layer][1][kp][n] = *reinterpret_cast<u32*>(&l2);
}

// ---------------------------------------------------------------------------
// Gather-aggregate: one warp per destination node (unchanged).
// ---------------------------------------------------------------------------
__global__ void gather_kernel(const float* __restrict__ h,
                              float* __restrict__ agg, int M) {
    int w = (blockIdx.x * blockDim.x + threadIdx.x) >> 5;
    int lane = threadIdx.x & 31;
    if (w >= M) return;
    int beg = g_off[w];
    int dg = g_degi[w];

    float4 a0 = make_float4(0.f, 0.f, 0.f, 0.f);
    float4 a1 = a0, a2 = a0, a3 = a0;
    int i = 0;
    for (; i + 4 <= dg; i += 4) {
        int s0 = g_ssrc[beg + i];
        int s1 = g_ssrc[beg + i + 1];
        int s2 = g_ssrc[beg + i + 2];
        int s3 = g_ssrc[beg + i + 3];
        float4 v0 = __ldg(reinterpret_cast<const float4*>(h + (size_t)s0 * D) + lane);
        float4 v1 = __ldg(reinterpret_cast<const float4*>(h + (size_t)s1 * D) + lane);
        float4 v2 = __ldg(reinterpret_cast<const float4*>(h + (size_t)s2 * D) + lane);
        float4 v3 = __ldg(reinterpret_cast<const float4*>(h + (size_t)s3 * D) + lane);
        a0.x += v0.x; a0.y += v0.y; a0.z += v0.z; a0.w += v0.w;
        a1.x += v1.x; a1.y += v1.y; a1.z += v1.z; a1.w += v1.w;
        a2.x += v2.x; a2.y += v2.y; a2.z += v2.z; a2.w += v2.w;
        a3.x += v3.x; a3.y += v3.y; a3.z += v3.z; a3.w += v3.w;
    }
    for (; i < dg; ++i) {
        int s = g_ssrc[beg + i];
        float4 v = __ldg(reinterpret_cast<const float4*>(h + (size_t)s * D) + lane);
        a0.x += v.x; a0.y += v.y; a0.z += v.z; a0.w += v.w;
    }
    float inv = (dg > 0) ? 1.0f / (float)dg : 0.0f;
    float4 r;
    r.x = (a0.x + a1.x + a2.x + a3.x) * inv;
    r.y = (a0.y + a1.y + a2.y + a3.y) * inv;
    r.z = (a0.z + a1.z + a2.z + a3.z) * inv;
    r.w = (a0.w + a1.w + a2.w + a3.w) * inv;
    *(reinterpret_cast<float4*>(agg + (size_t)w * D) + lane) = r;
}

// ---------------------------------------------------------------------------
// Fused SAGE GEMM via 3xBF16 mma.sync.m16n8k16, BM=64 x BN=128 tiles.
// out = Agg@Wl + H@Wr + mask.*bias (+ReLU).  8 warps (2x4), warp tile 32x32.
// B is pre-split/packed in global; staging is a pure coalesced copy.
// ---------------------------------------------------------------------------
#define MMA_BF16(c, a, b)                                                      \
    asm volatile(                                                              \
        "mma.sync.aligned.m16n8k16.row.col.f32.bf16.bf16.f32 "                 \
        "{%0,%1,%2,%3},{%4,%5,%6,%7},{%8,%9},{%0,%1,%2,%3};"                   \
        : "+f"((c)[0]), "+f"((c)[1]), "+f"((c)[2]), "+f"((c)[3])               \
        : "r"((a)[0]), "r"((a)[1]), "r"((a)[2]), "r"((a)[3]),                  \
          "r"((b)[0]), "r"((b)[1]))

#define AS_STRIDE 20   // 16 packed words + 4 pad
#define BS_STRIDE 136  // 128 packed cols + 8 pad

__device__ __forceinline__ void split2(float x, float y, u32& hi, u32& lo) {
    __nv_bfloat162 h2 = __floats2bfloat162_rn(x, y);
    float hx = __bfloat162float(__low2bfloat16(h2));
    float hy = __bfloat162float(__high2bfloat16(h2));
    __nv_bfloat162 l2 = __floats2bfloat162_rn(x - hx, y - hy);
    hi = *reinterpret_cast<u32*>(&h2);
    lo = *reinterpret_cast<u32*>(&l2);
}

template <bool RELU>
__global__ void __launch_bounds__(256, 3)
sage_mma_kernel(const float* __restrict__ Agg, const float* __restrict__ Hin,
                const u32* __restrict__ Bhi, const u32* __restrict__ Blo,
                const float* __restrict__ bias, float* __restrict__ out,
                int M) {
    __shared__ u32 As_hi[64 * AS_STRIDE];
    __shared__ u32 As_lo[64 * AS_STRIDE];
    __shared__ u32 Bs_hi[16 * BS_STRIDE];
    __shared__ u32 Bs_lo[16 * BS_STRIDE];

    const int tid = threadIdx.x;
    const int warp = tid >> 5;
    const int lane = tid & 31;
    const int gid = lane >> 2;          // 0..7
    const int tig = lane & 3;           // 0..3
    const int wm = (warp >> 2) * 32;    // warp m offset (0/32)
    const int wn = (warp & 3) * 32;     // warp n offset
    const int block_row = blockIdx.x * 64;

    // A staging: thread = (row 0..63, kgroup 0..3), 8 floats each
    const int alr = tid >> 2;
    const int akg = tid & 3;
    const int grow = block_row + alr;
    const bool rvalid = grow < M;
    // B staging: thread = (kp row 0..15, 8 cols), uint4 x2 per plane
    const int bkp = tid >> 4;
    const int bcn = (tid & 15) * 8;

    float acc[2][4][4];
#pragma unroll
    for (int i = 0; i < 2; ++i)
#pragma unroll
        for (int j = 0; j < 4; ++j)
#pragma unroll
            for (int r = 0; r < 4; ++r) acc[i][j][r] = 0.0f;

#pragma unroll 1
    for (int phase = 0; phase < 2; ++phase) {
        const float* A = phase ? Hin : Agg;
        const int kpbase_ph = phase * 64;

#pragma unroll 1
        for (int k0 = 0; k0 < D; k0 += 32) {
            // global loads
            float va[8];
            if (rvalid) {
                const float* ap = A + (size_t)grow * D + k0 + akg * 8;
                float4 t0 = __ldg(reinterpret_cast<const float4*>(ap));
                float4 t1 = __ldg(reinterpret_cast<const float4*>(ap + 4));
                va[0] = t0.x; va[1] = t0.y; va[2] = t0.z; va[3] = t0.w;
                va[4] = t1.x; va[5] = t1.y; va[6] = t1.z; va[7] = t1.w;
            } else {
#pragma unroll
                for (int q = 0; q < 8; ++q) va[q] = 0.0f;
            }
            const u32* bsrc_h = Bhi + (size_t)(kpbase_ph + k0 / 2 + bkp) * 128 + bcn;
            const u32* bsrc_l = Blo + (size_t)(kpbase_ph + k0 / 2 + bkp) * 128 + bcn;
            uint4 bh0 = __ldg(reinterpret_cast<const uint4*>(bsrc_h));
            uint4 bh1 = __ldg(reinterpret_cast<const uint4*>(bsrc_h + 4));
            uint4 bl0 = __ldg(reinterpret_cast<const uint4*>(bsrc_l));
            uint4 bl1 = __ldg(reinterpret_cast<const uint4*>(bsrc_l + 4));

            __syncthreads();
            // A split + store (4 packed words)
            {
                u32 hi[4], lo[4];
#pragma unroll
                for (int p = 0; p < 4; ++p) split2(va[2 * p], va[2 * p + 1], hi[p], lo[p]);
                u32 o = alr * AS_STRIDE + akg * 4;
#pragma unroll
                for (int p = 0; p < 4; ++p) { As_hi[o + p] = hi[p]; As_lo[o + p] = lo[p]; }
            }
            // B copy
            {
                u32 o = bkp * BS_STRIDE + bcn;
                *reinterpret_cast<uint4*>(&Bs_hi[o]) = bh0;
                *reinterpret_cast<uint4*>(&Bs_hi[o + 4]) = bh1;
                *reinterpret_cast<uint4*>(&Bs_lo[o]) = bl0;
                *reinterpret_cast<uint4*>(&Bs_lo[o + 4]) = bl1;
            }
            __syncthreads();

#pragma unroll
            for (int ks2 = 0; ks2 < 16; ks2 += 8) {   // two K=16 steps
                u32 bh[4][2], bl[4][2];
#pragma unroll
                for (int nt = 0; nt < 4; ++nt) {
                    int nc = wn + nt * 8 + gid;
                    bh[nt][0] = Bs_hi[(ks2 + tig) * BS_STRIDE + nc];
                    bh[nt][1] = Bs_hi[(ks2 + tig + 4) * BS_STRIDE + nc];
                    bl[nt][0] = Bs_lo[(ks2 + tig) * BS_STRIDE + nc];
                    bl[nt][1] = Bs_lo[(ks2 + tig + 4) * BS_STRIDE + nc];
                }
#pragma unroll
                for (int mt = 0; mt < 2; ++mt) {
                    int rr0 = (wm + mt * 16 + gid) * AS_STRIDE;
                    int rr8 = rr0 + 8 * AS_STRIDE;
                    u32 ah[4], al[4];
                    ah[0] = As_hi[rr0 + ks2 + tig];
                    ah[1] = As_hi[rr8 + ks2 + tig];
                    ah[2] = As_hi[rr0 + ks2 + tig + 4];
                    ah[3] = As_hi[rr8 + ks2 + tig + 4];
                    al[0] = As_lo[rr0 + ks2 + tig];
                    al[1] = As_lo[rr8 + ks2 + tig];
                    al[2] = As_lo[rr0 + ks2 + tig + 4];
                    al[3] = As_lo[rr8 + ks2 + tig + 4];
#pragma unroll
                    for (int nt = 0; nt < 4; ++nt) {
                        MMA_BF16(acc[mt][nt], ah, bh[nt]);
                        MMA_BF16(acc[mt][nt], ah, bl[nt]);
                        MMA_BF16(acc[mt][nt], al, bh[nt]);
                    }
                }
            }
        }
    }

    // Epilogue: + mask(deg>0)*bias, optional ReLU, float2 stores.
#pragma unroll
    for (int mt = 0; mt < 2; ++mt) {
#pragma unroll
        for (int nt = 0; nt < 4; ++nt) {
            int row0 = block_row + wm + mt * 16 + gid;
            int row1 = row0 + 8;
            int col = wn + nt * 8 + tig * 2;
            float b0v = bias[col];
            float b1v = bias[col + 1];
            if (row0 < M) {
                float m0 = (g_degi[row0] > 0) ? 1.0f : 0.0f;
                float x0 = acc[mt][nt][0] + m0 * b0v;
                float x1 = acc[mt][nt][1] + m0 * b1v;
                if (RELU) { x0 = fmaxf(x0, 0.0f); x1 = fmaxf(x1, 0.0f); }
                *reinterpret_cast<float2*>(out + (size_t)row0 * D + col) = make_float2(x0, x1);
            }
            if (row1 < M) {
                float m1 = (g_degi[row1] > 0) ? 1.0f : 0.0f;
                float x2 = acc[mt][nt][2] + m1 * b0v;
                float x3 = acc[mt][nt][3] + m1 * b1v;
                if (RELU) { x2 = fmaxf(x2, 0.0f); x3 = fmaxf(x3, 0.0f); }
                *reinterpret_cast<float2*>(out + (size_t)row1 * D + col) = make_float2(x2, x3);
            }
        }
    }
}

// ---------------------------------------------------------------------------
// Launch sequence (graph-capturable; all on default stream).
// ---------------------------------------------------------------------------
extern "C" void kernel_launch(void* const* d_in, const int* in_sizes, int n_in,
                              void* d_out, int out_size) {
    const float* x   = (const float*)d_in[0];
    const int*   ei  = (const int*)d_in[1];
    const float* W0l = (const float*)d_in[2];
    const float* b0l = (const float*)d_in[3];
    const float* W0r = (const float*)d_in[4];
    const float* W1l = (const float*)d_in[5];
    const float* b1l = (const float*)d_in[6];
    const float* W1r = (const float*)d_in[7];
    float* out = (float*)d_out;

    const int E = in_sizes[1] / 2;
    const int M = in_sizes[0] / D;
    const int* src = ei;
    const int* dst = ei + E;

    float* agg_ptr = nullptr;
    float* h_ptr = nullptr;
    u32* bp_ptr = nullptr;
    cudaGetSymbolAddress((void**)&agg_ptr, g_agg);
    cudaGetSymbolAddress((void**)&h_ptr, g_h);
    cudaGetSymbolAddress((void**)&bp_ptr, g_Bp);

    const int nb = (M + 255) / 256;
    const int eb = (E + 255) / 256;
    const int scanb = (M + SCAN_BLK - 1) / SCAN_BLK;
    const int gatherb = (M * 32 + 255) / 256;
    const int gemmb = (M + 63) / 64;
    const size_t plane = (size_t)128 * 128;   // u32 per plane

    // CSR build + weight conversion (once per launch)
    zero_int_kernel<<<nb, 256>>>(M);
    count_deg_kernel<<<eb, 256>>>(dst, E);
    convert_w_kernel<<<256, 128>>>(W0l, W0r, W1l, W1r);
    scan_part_kernel<<<scanb, SCAN_BLK>>>(M);
    scan_base_kernel<<<1, 32>>>(scanb);
    scan_write_kernel<<<scanb, SCAN_BLK>>>(M);
    fill_csr_kernel<<<eb, 256>>>(src, dst, E);

    // Layer 0
    gather_kernel<<<gatherb, 256>>>(x, agg_ptr, M);
    sage_mma_kernel<true><<<gemmb, 256>>>(
        agg_ptr, x, bp_ptr, bp_ptr + plane, b0l, h_ptr, M);

    // Layer 1
    gather_kernel<<<gatherb, 256>>>(h_ptr, agg_ptr, M);
    sage_mma_kernel<false><<<gemmb, 256>>>(
        agg_ptr, h_ptr, bp_ptr + 2 * plane, bp_ptr + 3 * plane, b1l, out, M);
}